// round 14
// baseline (speedup 1.0000x reference)
#include <cuda_runtime.h>
#include <cuda_fp16.h>
#include <math.h>
#include <stdint.h>

// ---------------------------------------------------------------------------
// MoE FFN (top-2 of 8, d_model=1024, d_hid=4096, T=4096), mma.sync fp16 path.
//
//   convert_x (+zero): x fp32 -> g_xh fp16
//   transpose_convert01: W0,W1 -> fp16 [E][N][K];  transpose_convert2: W2
//   routing / prefix / scatter
//   moe_gemm01: act = (Xg@W0+b0) * silu(Xg@W1+b1)   (fused, fp16 out)
//   moe_gemm2:  y   = act @ W2 + b2
//   combine
//
// Fused gemm01: 512 thr, 16 warps (2M x 8N), warp tile 64x16 per weight,
// dual accumulators (W0,W1) sharing one A tile -> A traffic halved and the
// fp32 u0 intermediate eliminated. cp.async 4-stage ring (wait_group 2),
// stage = A(10240)+B0(10240)+B1(10240), 80B pitch.
// ---------------------------------------------------------------------------

#define T_TOKENS 4096
#define DM 1024
#define DH 4096
#define NE 8
#define NROWS 9216

// ----- scratch -------------------------------------------------------------
__device__ __half g_acth[(size_t)NROWS * DH];     // act (fp16, gemm01 -> gemm2)
__device__ float  g_y[(size_t)NROWS * DM];
__device__ __half g_xh[(size_t)T_TOKENS * DM];
__device__ int    g_perm[NROWS];
__device__ int    g_tokrow[T_TOKENS * 2];
__device__ float  g_tokw[T_TOKENS * 2];
__device__ int    g_tokexp[T_TOKENS * 2];
__device__ int    g_cnt[NE];
__device__ int    g_run[NE];
__device__ int    g_abase[NE + 1];

__device__ __half g_w0[(size_t)NE * DH * DM];   // [E][N][K] fp16
__device__ __half g_w1[(size_t)NE * DH * DM];
__device__ __half g_w2[(size_t)NE * DM * DH];

// ----- helpers -------------------------------------------------------------
__device__ __forceinline__ uint32_t s2u(const void* p) {
    uint32_t a;
    asm("{ .reg .u64 t; cvta.to.shared.u64 t, %1; cvt.u32.u64 %0, t; }"
        : "=r"(a) : "l"(p));
    return a;
}
__device__ __forceinline__ void ldsm4(uint32_t* r, uint32_t addr) {
    asm volatile("ldmatrix.sync.aligned.m8n8.x4.shared.b16 {%0,%1,%2,%3}, [%4];"
                 : "=r"(r[0]), "=r"(r[1]), "=r"(r[2]), "=r"(r[3]) : "r"(addr));
}
__device__ __forceinline__ void mma16816(float* c, const uint32_t* a,
                                         uint32_t b0, uint32_t b1) {
    asm volatile(
        "mma.sync.aligned.m16n8k16.row.col.f32.f16.f16.f32 "
        "{%0,%1,%2,%3}, {%4,%5,%6,%7}, {%8,%9}, {%0,%1,%2,%3};"
        : "+f"(c[0]), "+f"(c[1]), "+f"(c[2]), "+f"(c[3])
        : "r"(a[0]), "r"(a[1]), "r"(a[2]), "r"(a[3]), "r"(b0), "r"(b1));
}
__device__ __forceinline__ void cpa16(uint32_t d, const void* g) {
    asm volatile("cp.async.cg.shared.global [%0], [%1], 16;" :: "r"(d), "l"(g));
}
__device__ __forceinline__ void cpa_commit() {
    asm volatile("cp.async.commit_group;" ::: "memory");
}
__device__ __forceinline__ void cpa_wait2() {
    asm volatile("cp.async.wait_group 2;" ::: "memory");
}

// ----- convert_x (+ counter zero) ------------------------------------------
__global__ void convert_x_kernel(const float* __restrict__ x) {
    if (blockIdx.x == 0 && threadIdx.x < NE) g_cnt[threadIdx.x] = 0;
    size_t i = ((size_t)blockIdx.x * blockDim.x + threadIdx.x) * 4;
    if (i >= (size_t)T_TOKENS * DM) return;
    float4 v = *(const float4*)(x + i);
    __half2 h0 = __floats2half2_rn(v.x, v.y);
    __half2 h1 = __floats2half2_rn(v.z, v.w);
    *(uint2*)(g_xh + i) = make_uint2(*(uint32_t*)&h0, *(uint32_t*)&h1);
}

// ----- routing (one warp per token) ----------------------------------------
__global__ void routing_kernel(const float* __restrict__ x,
                               const float* __restrict__ Wg,
                               const float* __restrict__ bg) {
    int warp = (blockIdx.x * blockDim.x + threadIdx.x) >> 5;
    int lane = threadIdx.x & 31;
    if (warp >= T_TOKENS) return;
    const float* xr = x + (size_t)warp * DM;

    float acc[8];
#pragma unroll
    for (int e = 0; e < 8; e++) acc[e] = 0.f;
    for (int d = lane; d < DM; d += 32) {
        float xv = xr[d];
        const float4* wp = (const float4*)(Wg + (size_t)d * 8);
        float4 wa = wp[0];
        float4 wb = wp[1];
        acc[0] += xv * wa.x; acc[1] += xv * wa.y;
        acc[2] += xv * wa.z; acc[3] += xv * wa.w;
        acc[4] += xv * wb.x; acc[5] += xv * wb.y;
        acc[6] += xv * wb.z; acc[7] += xv * wb.w;
    }
#pragma unroll
    for (int e = 0; e < 8; e++) {
        float v = acc[e];
        for (int o = 16; o; o >>= 1) v += __shfl_xor_sync(0xffffffffu, v, o);
        acc[e] = v;
    }
    if (lane == 0) {
        float lg[8];
#pragma unroll
        for (int e = 0; e < 8; e++) lg[e] = acc[e] + bg[e];
        float v0 = lg[0]; int i0 = 0;
#pragma unroll
        for (int e = 1; e < 8; e++) if (lg[e] > v0) { v0 = lg[e]; i0 = e; }
        float v1 = -3.4e38f; int i1 = -1;
#pragma unroll
        for (int e = 0; e < 8; e++)
            if (e != i0 && lg[e] > v1) { v1 = lg[e]; i1 = e; }
        float e1 = expf(v1 - v0);
        float w0 = 1.f / (1.f + e1);
        float w1 = e1 / (1.f + e1);
        int t = warp;
        g_tokexp[2 * t + 0] = i0;
        g_tokexp[2 * t + 1] = i1;
        g_tokw[2 * t + 0] = w0;
        g_tokw[2 * t + 1] = w1;
        atomicAdd(&g_cnt[i0], 1);
        atomicAdd(&g_cnt[i1], 1);
    }
}

// ----- prefix / scatter ----------------------------------------------------
__global__ void prefix_kernel() {
    if (threadIdx.x == 0) {
        int s = 0;
        for (int e = 0; e < NE; e++) {
            g_abase[e] = s;
            g_run[e] = s;
            s += (g_cnt[e] + 127) & ~127;
        }
        g_abase[NE] = s;
    }
}
__global__ void scatter_kernel() {
    int t = blockIdx.x * blockDim.x + threadIdx.x;
    if (t >= T_TOKENS) return;
#pragma unroll
    for (int k = 0; k < 2; k++) {
        int e = g_tokexp[2 * t + k];
        int pos = atomicAdd(&g_run[e], 1);
        g_perm[pos] = t;
        g_tokrow[2 * t + k] = pos;
    }
}

// ----- transpose + convert: W0 and W1 in one launch ------------------------
__global__ void transpose_convert01(const float* __restrict__ W0,
                                    const float* __restrict__ W1) {
    const int K = DM, N = DH;
    int ez = blockIdx.z;                 // 0..15: expert*2 + which
    int e = ez >> 1;
    const float* W = (ez & 1) ? W1 : W0;
    __half* oh = (ez & 1) ? g_w1 : g_w0;
    __shared__ float tile[32][33];
    int n0 = blockIdx.x * 32, k0 = blockIdx.y * 32;
    int tx = threadIdx.x, ty = threadIdx.y;  // 32 x 8
    const float* src = W + ((size_t)e * K + k0) * N + n0 + tx;
#pragma unroll
    for (int i = 0; i < 4; i++)
        tile[ty + 8 * i][tx] = src[(size_t)(ty + 8 * i) * N];
    __syncthreads();
    size_t ob = ((size_t)e * N + n0) * K + k0 + tx;
#pragma unroll
    for (int i = 0; i < 4; i++) {
        int nl = ty + 8 * i;
        oh[ob + (size_t)nl * K] = __float2half_rn(tile[tx][nl]);
    }
}
__global__ void transpose_convert2(const float* __restrict__ W) {
    const int K = DH, N = DM;
    __shared__ float tile[32][33];
    int e = blockIdx.z;
    int n0 = blockIdx.x * 32, k0 = blockIdx.y * 32;
    int tx = threadIdx.x, ty = threadIdx.y;
    const float* src = W + ((size_t)e * K + k0) * N + n0 + tx;
#pragma unroll
    for (int i = 0; i < 4; i++)
        tile[ty + 8 * i][tx] = src[(size_t)(ty + 8 * i) * N];
    __syncthreads();
    size_t ob = ((size_t)e * N + n0) * K + k0 + tx;
#pragma unroll
    for (int i = 0; i < 4; i++) {
        int nl = ty + 8 * i;
        g_w2[ob + (size_t)nl * K] = __float2half_rn(tile[tx][nl]);
    }
}

#define PITCH 80

// ----- fused gemm0+gemm1 (512 threads, dual accumulators) ------------------
// Stage (30720 B): A[0) B0[10240) B1[20480); 80 B row pitch; 4-stage ring.
#define STG01 30720
#define SMEM01 (4 * STG01)

__global__ void __launch_bounds__(512, 1)
moe_gemm01(const float* __restrict__ bias0all,
           const float* __restrict__ bias1all) {
    const int KD = DM, NN = DH;

    const int r0 = blockIdx.y * 128;
    if (r0 >= g_abase[NE]) return;
    int e = 0;
    while (e < NE - 1 && r0 >= g_abase[e + 1]) e++;
    int vend = g_abase[e] + g_cnt[e] - r0;
    if (vend <= 0) return;
    if (vend > 128) vend = 128;
    const int n0 = blockIdx.x * 128;

    extern __shared__ char smem_raw[];
    const uint32_t sb = s2u(smem_raw);

    const int tid = threadIdx.x;
    const int w = tid >> 5;
    const int lane = tid & 31;
    const int wm = w & 1;        // M half
    const int wn = w >> 1;       // 0..7, 16-col slice

    // ---- cp.async mapping:
    //   tid   0-255: A rows (2 thr/row, 32B each)
    //   tid 256-383: B0 rows (1 thr/row, 64B)
    //   tid 384-511: B1 rows (1 thr/row, 64B)
    const char* gsrc;
    uint32_t dst_off;
    int ncp;
    if (tid < 256) {
        int row_i = tid >> 1, coff = (tid & 1) * 32;
        gsrc = (const char*)(g_xh + (size_t)g_perm[r0 + row_i] * DM) + coff;
        dst_off = (uint32_t)(row_i * PITCH + coff);
        ncp = 2;
    } else if (tid < 384) {
        int r = tid - 256;
        gsrc = (const char*)(g_w0 + ((size_t)e * NN + n0 + r) * KD);
        dst_off = 10240u + (uint32_t)(r * PITCH);
        ncp = 4;
    } else {
        int r = tid - 384;
        gsrc = (const char*)(g_w1 + ((size_t)e * NN + n0 + r) * KD);
        dst_off = 20480u + (uint32_t)(r * PITCH);
        ncp = 4;
    }

    const int S = KD / 32;  // 32

    auto issue = [&](int s) {
        if (s < S) {
            uint32_t d = sb + (uint32_t)(s & 3) * STG01 + dst_off;
            size_t go = (size_t)s * 64;
#pragma unroll
            for (int c = 0; c < 4; c++)
                if (c < ncp) cpa16(d + 16u * c, gsrc + go + 16 * c);
        }
        cpa_commit();
    };

    // ---- ldmatrix offsets
    const uint32_t a_ld = (uint32_t)((wm * 64 + (lane & 15)) * PITCH +
                                     ((lane >> 4) * 8) * 2);
    const uint32_t b_ld = (uint32_t)((wn * 16 + (lane & 7) + ((lane >> 4) & 1) * 8) * PITCH +
                                     (((lane >> 3) & 1) * 8) * 2);

    float acc[2][4][2][4];  // weight, mf, nf, frag
#pragma unroll
    for (int g = 0; g < 2; g++)
#pragma unroll
        for (int i = 0; i < 4; i++)
#pragma unroll
            for (int j = 0; j < 2; j++)
#pragma unroll
                for (int q = 0; q < 4; q++) acc[g][i][j][q] = 0.f;

    issue(0);
    issue(1);
    issue(2);

    for (int s = 0; s < S; s++) {
        cpa_wait2();
        __syncthreads();
        const uint32_t bb = sb + (uint32_t)(s & 3) * STG01;
#pragma unroll
        for (int ks = 0; ks < 2; ks++) {
            const uint32_t ko = (uint32_t)(ks * 32);
            uint32_t ah[4][4], b0f[4], b1f[4];
#pragma unroll
            for (int mf = 0; mf < 4; mf++)
                ldsm4(ah[mf], bb + a_ld + (uint32_t)(mf * 16 * PITCH) + ko);
            ldsm4(b0f, bb + 10240u + b_ld + ko);
            ldsm4(b1f, bb + 20480u + b_ld + ko);
#pragma unroll
            for (int mf = 0; mf < 4; mf++)
#pragma unroll
                for (int sub = 0; sub < 2; sub++) {
                    mma16816(acc[0][mf][sub], ah[mf], b0f[2 * sub], b0f[2 * sub + 1]);
                    mma16816(acc[1][mf][sub], ah[mf], b1f[2 * sub], b1f[2 * sub + 1]);
                }
        }
        issue(s + 3);
    }

    // ---- epilogue: act = (u0+b0) * silu(u1+b1) -> fp16 ----------------------
    const float* bias0 = bias0all + (size_t)e * NN + n0;
    const float* bias1 = bias1all + (size_t)e * NN + n0;
#pragma unroll
    for (int mf = 0; mf < 4; mf++) {
        int mbase = wm * 64 + mf * 16 + (lane >> 2);
#pragma unroll
        for (int half = 0; half < 2; half++) {
            int m = mbase + half * 8;
            if (m >= vend) continue;
            size_t r = (size_t)(r0 + m);
#pragma unroll
            for (int nf = 0; nf < 2; nf++) {
                int col = wn * 16 + nf * 8 + (lane & 3) * 2;
                float h0 = acc[0][mf][nf][2 * half + 0] + bias0[col];
                float h1 = acc[0][mf][nf][2 * half + 1] + bias0[col + 1];
                float u0 = acc[1][mf][nf][2 * half + 0] + bias1[col];
                float u1 = acc[1][mf][nf][2 * half + 1] + bias1[col + 1];
                float v0 = h0 * (u0 / (1.f + expf(-u0)));
                float v1 = h1 * (u1 / (1.f + expf(-u1)));
                __half2 hv = __floats2half2_rn(v0, v1);
                *(uint32_t*)(g_acth + r * DH + n0 + col) = *(uint32_t*)&hv;
            }
        }
    }
}

// ----- gemm2 (unchanged structure: 256 thr, occ 2) -------------------------
#define STG2 20480
#define SMEM2 (4 * STG2)

__global__ void __launch_bounds__(256, 2)
moe_gemm2(const float* __restrict__ biasall) {
    const int KD = DH, NN = DM;

    const int r0 = blockIdx.y * 128;
    if (r0 >= g_abase[NE]) return;
    int e = 0;
    while (e < NE - 1 && r0 >= g_abase[e + 1]) e++;
    int vend = g_abase[e] + g_cnt[e] - r0;
    if (vend <= 0) return;
    if (vend > 128) vend = 128;
    const int n0 = blockIdx.x * 128;

    extern __shared__ char smem_raw[];
    const uint32_t sb = s2u(smem_raw);

    const int tid = threadIdx.x;
    const int w = tid >> 5;
    const int lane = tid & 31;
    const int wm = w & 1;
    const int wn = w >> 1;

    const int row_i = tid >> 1;
    const int coff = (tid & 1) * 32;
    const char* ag = (const char*)(g_acth + (size_t)(r0 + row_i) * DH) + coff;
    const char* bg = (const char*)(g_w2 + ((size_t)e * NN + n0 + row_i) * KD) + coff;
    const uint32_t stoff = (uint32_t)(row_i * PITCH + coff);

    const int S = KD / 32;  // 128

    auto issue = [&](int s) {
        if (s < S) {
            uint32_t d = sb + (uint32_t)(s & 3) * STG2 + stoff;
            size_t go = (size_t)s * 64;
            cpa16(d, ag + go);
            cpa16(d + 16, ag + go + 16);
            cpa16(d + 10240, bg + go);
            cpa16(d + 10256, bg + go + 16);
        }
        cpa_commit();
    };

    const uint32_t a_ld = (uint32_t)((wm * 64 + (lane & 15)) * PITCH +
                                     ((lane >> 4) * 8) * 2);
    const uint32_t b_ld = (uint32_t)((wn * 32 + (lane & 7) + ((lane >> 4) & 1) * 8) * PITCH +
                                     (((lane >> 3) & 1) * 8) * 2);

    float acc[4][4][4];
#pragma unroll
    for (int i = 0; i < 4; i++)
#pragma unroll
        for (int j = 0; j < 4; j++)
#pragma unroll
            for (int q = 0; q < 4; q++) acc[i][j][q] = 0.f;

    issue(0);
    issue(1);
    issue(2);

    for (int s = 0; s < S; s++) {
        cpa_wait2();
        __syncthreads();
        const uint32_t bb = sb + (uint32_t)(s & 3) * STG2;
#pragma unroll
        for (int ks = 0; ks < 2; ks++) {
            const uint32_t ko = (uint32_t)(ks * 32);
            uint32_t ah[4][4], bh[2][4];
#pragma unroll
            for (int mf = 0; mf < 4; mf++)
                ldsm4(ah[mf], bb + a_ld + (uint32_t)(mf * 16 * PITCH) + ko);
#pragma unroll
            for (int p = 0; p < 2; p++)
                ldsm4(bh[p], bb + 10240u + b_ld + (uint32_t)(p * 16 * PITCH) + ko);
#pragma unroll
            for (int mf = 0; mf < 4; mf++)
#pragma unroll
                for (int p = 0; p < 2; p++)
#pragma unroll
                    for (int sub = 0; sub < 2; sub++)
                        mma16816(acc[mf][p * 2 + sub], ah[mf],
                                 bh[p][2 * sub], bh[p][2 * sub + 1]);
        }
        issue(s + 3);
    }

    const float* bias = biasall + (size_t)e * NN + n0;
#pragma unroll
    for (int mf = 0; mf < 4; mf++) {
        int mbase = wm * 64 + mf * 16 + (lane >> 2);
#pragma unroll
        for (int half = 0; half < 2; half++) {
            int m = mbase + half * 8;
            if (m >= vend) continue;
            size_t r = (size_t)(r0 + m);
#pragma unroll
            for (int nf = 0; nf < 4; nf++) {
                int col = wn * 32 + nf * 8 + (lane & 3) * 2;
                float c0 = acc[mf][nf][2 * half + 0] + bias[col];
                float c1 = acc[mf][nf][2 * half + 1] + bias[col + 1];
                *(float2*)(g_y + r * DM + n0 + col) = make_float2(c0, c1);
            }
        }
    }
}

// ----- combine -------------------------------------------------------------
__global__ void combine_kernel(float* __restrict__ out) {
    int t = blockIdx.x;
    int d4 = threadIdx.x;
    int r0 = g_tokrow[2 * t + 0];
    int r1 = g_tokrow[2 * t + 1];
    float w0 = g_tokw[2 * t + 0];
    float w1 = g_tokw[2 * t + 1];
    const float4 y0 = *(const float4*)(g_y + (size_t)r0 * DM + d4 * 4);
    const float4 y1 = *(const float4*)(g_y + (size_t)r1 * DM + d4 * 4);
    float4 o;
    o.x = w0 * y0.x + w1 * y1.x;
    o.y = w0 * y0.y + w1 * y1.y;
    o.z = w0 * y0.z + w1 * y1.z;
    o.w = w0 * y0.w + w1 * y1.w;
    *(float4*)(out + (size_t)t * DM + d4 * 4) = o;
}

// ---------------------------------------------------------------------------
extern "C" void kernel_launch(void* const* d_in, const int* in_sizes, int n_in,
                              void* d_out, int out_size) {
    (void)in_sizes; (void)n_in; (void)out_size;
    const float* x  = (const float*)d_in[0];
    const float* Wg = (const float*)d_in[1];
    const float* bg = (const float*)d_in[2];
    const float* W0 = (const float*)d_in[3];
    const float* b0 = (const float*)d_in[4];
    const float* W1 = (const float*)d_in[5];
    const float* b1 = (const float*)d_in[6];
    const float* W2 = (const float*)d_in[7];
    const float* b2 = (const float*)d_in[8];
    float* out = (float*)d_out;

    cudaFuncSetAttribute(moe_gemm01,
                         cudaFuncAttributeMaxDynamicSharedMemorySize, SMEM01);
    cudaFuncSetAttribute(moe_gemm2,
                         cudaFuncAttributeMaxDynamicSharedMemorySize, SMEM2);

    convert_x_kernel<<<T_TOKENS * DM / (256 * 4), 256>>>(x);

    dim3 tb(32, 8);
    transpose_convert01<<<dim3(DH / 32, DM / 32, NE * 2), tb>>>(W0, W1);
    transpose_convert2<<<dim3(DM / 32, DH / 32, NE), tb>>>(W2);

    routing_kernel<<<T_TOKENS / 8, 256>>>(x, Wg, bg);
    prefix_kernel<<<1, 32>>>();
    scatter_kernel<<<T_TOKENS / 256, 256>>>();

    moe_gemm01<<<dim3(DH / 128, NROWS / 128), 512, SMEM01>>>(b0, b1);
    moe_gemm2<<<dim3(DM / 128, NROWS / 128), 256, SMEM2>>>(b2);

    combine_kernel<<<T_TOKENS, 256>>>(out);
}